// round 5
// baseline (speedup 1.0000x reference)
#include <cuda_runtime.h>
#include <math.h>
#include <stdint.h>

#define BB 2
#define SS 2048
#define DD 1024
#define HH 16
#define MM (BB*SS)

// Scratch (allocation-free rule: __device__ globals)
__device__ float g_Q[(size_t)MM * DD];
__device__ float g_K[(size_t)MM * DD];
__device__ float g_V[(size_t)MM * DD];
__device__ float g_ctx[(size_t)MM * DD];

__device__ __forceinline__ uint32_t f2tf(float f) {
    uint32_t u; asm("cvt.rna.tf32.f32 %0, %1;" : "=r"(u) : "f"(f)); return u;
}
__device__ __forceinline__ void mma8(float* d, const uint32_t* a, const uint32_t* b) {
    asm volatile(
        "mma.sync.aligned.m16n8k8.row.col.f32.tf32.tf32.f32 "
        "{%0,%1,%2,%3}, {%4,%5,%6,%7}, {%8,%9}, {%0,%1,%2,%3};\n"
        : "+f"(d[0]), "+f"(d[1]), "+f"(d[2]), "+f"(d[3])
        : "r"(a[0]), "r"(a[1]), "r"(a[2]), "r"(a[3]), "r"(b[0]), "r"(b[1]));
}

// ===========================================================================
// GEMM: C = A @ W + bias (tf32 mma.sync).
// Block 128x64, BK=32, 256 threads = 8 warps of 32x32.
// Ping-pong SMEM (1 barrier/chunk); grid.z selects one of up to 3 problems.
// ===========================================================================
#define GPA 36
#define GPB 72
#define GA_SZ (128 * GPA)           // one A buffer (uint32 elems)
#define GB_SZ (32 * GPB)
#define GEMM_SMEM ((2 * GA_SZ + 2 * GB_SZ) * 4)   // 55296 B

__global__ void __launch_bounds__(256) gemm_tc(
    const float* __restrict__ A0, const float* __restrict__ A1, const float* __restrict__ A2,
    const float* __restrict__ W0, const float* __restrict__ W1, const float* __restrict__ W2,
    const float* __restrict__ b0, const float* __restrict__ b1, const float* __restrict__ b2,
    float* __restrict__ C0, float* __restrict__ C1, float* __restrict__ C2)
{
    extern __shared__ uint32_t gsm[];
    const int z = blockIdx.z;
    const float* A = (z == 0) ? A0 : (z == 1) ? A1 : A2;
    const float* W = (z == 0) ? W0 : (z == 1) ? W1 : W2;
    const float* bias = (z == 0) ? b0 : (z == 1) ? b1 : b2;
    float* C = (z == 0) ? C0 : (z == 1) ? C1 : C2;

    const int tid  = threadIdx.x;
    const int lane = tid & 31, warp = tid >> 5;
    const int g = lane >> 2, tig = lane & 3;
    const int wm = warp >> 1, wn = warp & 1;
    const int row0 = blockIdx.y * 128, col0 = blockIdx.x * 64;

    const int rA = tid >> 3, cA = (tid & 7) * 4;
    const int rB = tid >> 4, cB = (tid & 15) * 4;
    const float* Ap = A + (size_t)(row0 + rA) * DD + cA;
    const float* Wp = W + (size_t)rB * DD + col0 + cB;

    float acc[2][4][4] = {};
    float4 av[4], wv[2];

    // ---- prologue: chunk 0 -> buf 0 ----
    #pragma unroll
    for (int i = 0; i < 4; i++) av[i] = *(const float4*)(Ap + (size_t)(32 * i) * DD);
    #pragma unroll
    for (int i = 0; i < 2; i++) wv[i] = *(const float4*)(Wp + (size_t)(16 * i) * DD);
    {
        uint32_t* As = gsm;
        uint32_t* Bs = gsm + 2 * GA_SZ;
        #pragma unroll
        for (int i = 0; i < 4; i++)
            *(uint4*)&As[(rA + 32 * i) * GPA + cA] =
                make_uint4(f2tf(av[i].x), f2tf(av[i].y), f2tf(av[i].z), f2tf(av[i].w));
        #pragma unroll
        for (int i = 0; i < 2; i++)
            *(uint4*)&Bs[(rB + 16 * i) * GPB + cB] =
                make_uint4(f2tf(wv[i].x), f2tf(wv[i].y), f2tf(wv[i].z), f2tf(wv[i].w));
    }
    __syncthreads();

    for (int c = 0; c < 32; c++) {
        // issue next-chunk global loads early (hidden under MMA loop)
        if (c + 1 < 32) {
            const int k0 = (c + 1) * 32;
            #pragma unroll
            for (int i = 0; i < 4; i++)
                av[i] = *(const float4*)(Ap + k0 + (size_t)(32 * i) * DD);
            #pragma unroll
            for (int i = 0; i < 2; i++)
                wv[i] = *(const float4*)(Wp + (size_t)(k0 + 16 * i) * DD);
        }

        const uint32_t* As = gsm + (c & 1) * GA_SZ;
        const uint32_t* Bs = gsm + 2 * GA_SZ + (c & 1) * GB_SZ;

        #pragma unroll
        for (int kk = 0; kk < 4; kk++) {
            const int kb = kk * 8;
            uint32_t af[2][4], bf[4][2];
            #pragma unroll
            for (int mt = 0; mt < 2; mt++) {
                const int r = wm * 32 + mt * 16 + g;
                af[mt][0] = As[r * GPA + kb + tig];
                af[mt][1] = As[(r + 8) * GPA + kb + tig];
                af[mt][2] = As[r * GPA + kb + tig + 4];
                af[mt][3] = As[(r + 8) * GPA + kb + tig + 4];
            }
            #pragma unroll
            for (int j = 0; j < 4; j++) {
                const int n = wn * 32 + j * 8 + g;
                bf[j][0] = Bs[(kb + tig) * GPB + n];
                bf[j][1] = Bs[(kb + tig + 4) * GPB + n];
            }
            #pragma unroll
            for (int mt = 0; mt < 2; mt++)
                #pragma unroll
                for (int j = 0; j < 4; j++)
                    mma8(acc[mt][j], af[mt], bf[j]);
        }

        // store next chunk into the other buffer, then single barrier
        if (c + 1 < 32) {
            uint32_t* Asn = gsm + ((c + 1) & 1) * GA_SZ;
            uint32_t* Bsn = gsm + 2 * GA_SZ + ((c + 1) & 1) * GB_SZ;
            #pragma unroll
            for (int i = 0; i < 4; i++)
                *(uint4*)&Asn[(rA + 32 * i) * GPA + cA] =
                    make_uint4(f2tf(av[i].x), f2tf(av[i].y), f2tf(av[i].z), f2tf(av[i].w));
            #pragma unroll
            for (int i = 0; i < 2; i++)
                *(uint4*)&Bsn[(rB + 16 * i) * GPB + cB] =
                    make_uint4(f2tf(wv[i].x), f2tf(wv[i].y), f2tf(wv[i].z), f2tf(wv[i].w));
            __syncthreads();
        }
    }

    // epilogue
    #pragma unroll
    for (int mt = 0; mt < 2; mt++) {
        #pragma unroll
        for (int j = 0; j < 4; j++) {
            const int n = col0 + wn * 32 + j * 8 + 2 * tig;
            const float bb0 = bias[n], bb1 = bias[n + 1];
            const int r = row0 + wm * 32 + mt * 16 + g;
            *(float2*)&C[(size_t)r * DD + n] =
                make_float2(acc[mt][j][0] + bb0, acc[mt][j][1] + bb1);
            *(float2*)&C[(size_t)(r + 8) * DD + n] =
                make_float2(acc[mt][j][2] + bb0, acc[mt][j][3] + bb1);
        }
    }
}

// ===========================================================================
// Flash attention, tf32 mma.sync.
// CTA = (128-row q-tile, b, h). 256 threads = 8 warps x 16 q-rows.
// Ping-pong K/V buffers, 1 barrier per key-tile. P kept in registers and
// transposed to PV A-fragments via quad shuffles (no SMEM round trip).
// SMEM: Ks[2][64][72] + Vs[2][64][72] = 73728 B (Q staged over Ks in prologue)
// ===========================================================================
#define APK 72
#define TSZ (64 * APK)                 // one tile buffer (uint32 elems)
#define ATTN_SMEM (4 * TSZ * 4)        // 73728 B

__global__ void __launch_bounds__(256) attn_tc()
{
    extern __shared__ uint32_t smem_u[];

    const int tid  = threadIdx.x;
    const int lane = tid & 31, warp = tid >> 5;
    const int g = lane >> 2, tig = lane & 3;
    const int qt = blockIdx.x;
    const int b  = blockIdx.y >> 4;
    const int h  = blockIdx.y & 15;

    const float* Qg = g_Q + (size_t)(b * SS + qt * 128) * DD + h * 64;
    const float* Kg = g_K + (size_t)(b * SS) * DD + h * 64;
    const float* Vg = g_V + (size_t)(b * SS) * DD + h * 64;

    // ---- stage Q (scaled) into smem (overlays the two K buffers) ----
    {
        float* Qst = (float*)smem_u;
        const int r = tid >> 4, c = (tid & 15) * 4;
        #pragma unroll
        for (int i = 0; i < 8; i++) {
            float4 qv = *(const float4*)(Qg + (size_t)(r + 16 * i) * DD + c);
            qv.x *= 0.125f; qv.y *= 0.125f; qv.z *= 0.125f; qv.w *= 0.125f;
            *(float4*)&Qst[(r + 16 * i) * APK + c] = qv;
        }
    }
    __syncthreads();

    const int qrow = warp * 16 + g;
    uint32_t qa[8][4];
    {
        const float* Qst = (const float*)smem_u;
        #pragma unroll
        for (int kt8 = 0; kt8 < 8; kt8++) {
            qa[kt8][0] = f2tf(Qst[qrow * APK + kt8 * 8 + tig]);
            qa[kt8][1] = f2tf(Qst[(qrow + 8) * APK + kt8 * 8 + tig]);
            qa[kt8][2] = f2tf(Qst[qrow * APK + kt8 * 8 + tig + 4]);
            qa[kt8][3] = f2tf(Qst[(qrow + 8) * APK + kt8 * 8 + tig + 4]);
        }
    }
    __syncthreads();   // Q reads done before K buffer reuse

    // ---- fill tile 0 into buffer 0 ----
    {
        uint32_t* Ks = smem_u;                // buf 0
        uint32_t* Vs = smem_u + 2 * TSZ;      // buf 0
        const int ck = tid & 63, fq = tid >> 6;
        #pragma unroll
        for (int g2 = 0; g2 < 4; g2++) {
            const int f = fq * 4 + g2;
            float4 kv = *(const float4*)(Kg + (size_t)ck * DD + 4 * f);
            Ks[(4 * f + 0) * APK + ck] = f2tf(kv.x);
            Ks[(4 * f + 1) * APK + ck] = f2tf(kv.y);
            Ks[(4 * f + 2) * APK + ck] = f2tf(kv.z);
            Ks[(4 * f + 3) * APK + ck] = f2tf(kv.w);
        }
        const int rv = tid >> 4, cv = (tid & 15) * 4;
        #pragma unroll
        for (int i = 0; i < 4; i++) {
            float4 vv = *(const float4*)(Vg + (size_t)(rv + 16 * i) * DD + cv);
            *(uint4*)&Vs[(rv + 16 * i) * APK + cv] =
                make_uint4(f2tf(vv.x), f2tf(vv.y), f2tf(vv.z), f2tf(vv.w));
        }
    }
    __syncthreads();

    float of[8][4] = {};
    float mrow[2] = {-1e30f, -1e30f};
    float lrow[2] = {0.f, 0.f};

    for (int kt = 0; kt < SS / 64; kt++) {
        const uint32_t* Ks = smem_u + (kt & 1) * TSZ;
        const uint32_t* Vs = smem_u + 2 * TSZ + (kt & 1) * TSZ;

        // ---- S = Qs @ K^T  (interchanged: 8 independent MMAs per kt8) ----
        float sf[8][4] = {};
        #pragma unroll
        for (int kt8 = 0; kt8 < 8; kt8++) {
            const int kr = kt8 * 8 + tig;
            uint32_t bb0[8], bb1[8];
            #pragma unroll
            for (int j = 0; j < 8; j++) {
                bb0[j] = Ks[kr * APK + j * 8 + g];
                bb1[j] = Ks[(kr + 4) * APK + j * 8 + g];
            }
            #pragma unroll
            for (int j = 0; j < 8; j++) {
                uint32_t bb[2] = {bb0[j], bb1[j]};
                mma8(sf[j], qa[kt8], bb);
            }
        }

        // ---- online softmax ----
        float corr[2];
        #pragma unroll
        for (int i = 0; i < 2; i++) {
            float mx = -1e30f;
            #pragma unroll
            for (int j = 0; j < 8; j++)
                mx = fmaxf(mx, fmaxf(sf[j][2 * i], sf[j][2 * i + 1]));
            mx = fmaxf(mx, __shfl_xor_sync(0xffffffffu, mx, 1));
            mx = fmaxf(mx, __shfl_xor_sync(0xffffffffu, mx, 2));
            const float mn = fmaxf(mrow[i], mx);
            corr[i] = __expf(mrow[i] - mn);
            mrow[i] = mn;
            float rs = 0.f;
            #pragma unroll
            for (int j = 0; j < 8; j++) {
                sf[j][2 * i]     = __expf(sf[j][2 * i] - mn);
                sf[j][2 * i + 1] = __expf(sf[j][2 * i + 1] - mn);
                rs += sf[j][2 * i] + sf[j][2 * i + 1];
            }
            rs += __shfl_xor_sync(0xffffffffu, rs, 1);
            rs += __shfl_xor_sync(0xffffffffu, rs, 2);
            lrow[i] = lrow[i] * corr[i] + rs;
        }
        #pragma unroll
        for (int j = 0; j < 8; j++) {
            of[j][0] *= corr[0]; of[j][1] *= corr[0];
            of[j][2] *= corr[1]; of[j][3] *= corr[1];
        }

        // ---- O += P @ V : P transposed C-frag -> A-frag via quad shuffles ----
        const int srcA = (lane & 28) | (tig >> 1);
        const int srcB = srcA + 2;
        const bool odd = (tig & 1) != 0;
        #pragma unroll
        for (int kt8 = 0; kt8 < 8; kt8++) {
            const float v00 = __shfl_sync(0xffffffffu, sf[kt8][0], srcA);
            const float v01 = __shfl_sync(0xffffffffu, sf[kt8][1], srcA);
            const float v10 = __shfl_sync(0xffffffffu, sf[kt8][2], srcA);
            const float v11 = __shfl_sync(0xffffffffu, sf[kt8][3], srcA);
            const float w00 = __shfl_sync(0xffffffffu, sf[kt8][0], srcB);
            const float w01 = __shfl_sync(0xffffffffu, sf[kt8][1], srcB);
            const float w10 = __shfl_sync(0xffffffffu, sf[kt8][2], srcB);
            const float w11 = __shfl_sync(0xffffffffu, sf[kt8][3], srcB);
            uint32_t pa[4];
            pa[0] = f2tf(odd ? v01 : v00);
            pa[1] = f2tf(odd ? v11 : v10);
            pa[2] = f2tf(odd ? w01 : w00);
            pa[3] = f2tf(odd ? w11 : w10);

            const int vr = kt8 * 8 + tig;
            #pragma unroll
            for (int j = 0; j < 8; j++) {
                uint32_t bb[2];
                bb[0] = Vs[vr * APK + j * 8 + g];
                bb[1] = Vs[(vr + 4) * APK + j * 8 + g];
                mma8(of[j], pa, bb);
            }
        }

        // ---- fill next tile into the other buffer, single barrier ----
        if (kt + 1 < SS / 64) {
            uint32_t* Ksn = smem_u + ((kt + 1) & 1) * TSZ;
            uint32_t* Vsn = smem_u + 2 * TSZ + ((kt + 1) & 1) * TSZ;
            const float* Kt = Kg + (size_t)((kt + 1) * 64) * DD;
            const float* Vt = Vg + (size_t)((kt + 1) * 64) * DD;
            const int ck = tid & 63, fq = tid >> 6;
            #pragma unroll
            for (int g2 = 0; g2 < 4; g2++) {
                const int f = fq * 4 + g2;
                float4 kv = *(const float4*)(Kt + (size_t)ck * DD + 4 * f);
                Ksn[(4 * f + 0) * APK + ck] = f2tf(kv.x);
                Ksn[(4 * f + 1) * APK + ck] = f2tf(kv.y);
                Ksn[(4 * f + 2) * APK + ck] = f2tf(kv.z);
                Ksn[(4 * f + 3) * APK + ck] = f2tf(kv.w);
            }
            const int rv = tid >> 4, cv = (tid & 15) * 4;
            #pragma unroll
            for (int i = 0; i < 4; i++) {
                float4 vv = *(const float4*)(Vt + (size_t)(rv + 16 * i) * DD + cv);
                *(uint4*)&Vsn[(rv + 16 * i) * APK + cv] =
                    make_uint4(f2tf(vv.x), f2tf(vv.y), f2tf(vv.z), f2tf(vv.w));
            }
            __syncthreads();
        }
    }

    // ---- normalize + write context ----
    const float inv0 = 1.f / lrow[0], inv1 = 1.f / lrow[1];
    const size_t orow = (size_t)(b * SS + qt * 128 + qrow);
    #pragma unroll
    for (int j = 0; j < 8; j++) {
        const int n = h * 64 + j * 8 + 2 * tig;
        *(float2*)&g_ctx[orow * DD + n] =
            make_float2(of[j][0] * inv0, of[j][1] * inv0);
        *(float2*)&g_ctx[(orow + 8) * DD + n] =
            make_float2(of[j][2] * inv1, of[j][3] * inv1);
    }
}

// ---------------------------------------------------------------------------
extern "C" void kernel_launch(void* const* d_in, const int* in_sizes, int n_in,
                              void* d_out, int out_size)
{
    (void)in_sizes; (void)n_in; (void)out_size;
    const float* q  = (const float*)d_in[0];
    const float* k  = (const float*)d_in[1];
    const float* v  = (const float*)d_in[2];
    const float* wq = (const float*)d_in[3];
    const float* bq = (const float*)d_in[4];
    const float* wk = (const float*)d_in[5];
    const float* bk = (const float*)d_in[6];
    const float* wv = (const float*)d_in[7];
    const float* bv = (const float*)d_in[8];
    const float* wo = (const float*)d_in[9];
    const float* bo = (const float*)d_in[10];
    float* out = (float*)d_out;

    float *gq, *gk, *gv, *gctx;
    cudaGetSymbolAddress((void**)&gq,   g_Q);
    cudaGetSymbolAddress((void**)&gk,   g_K);
    cudaGetSymbolAddress((void**)&gv,   g_V);
    cudaGetSymbolAddress((void**)&gctx, g_ctx);

    cudaFuncSetAttribute(gemm_tc, cudaFuncAttributeMaxDynamicSharedMemorySize, GEMM_SMEM);
    cudaFuncSetAttribute(attn_tc, cudaFuncAttributeMaxDynamicSharedMemorySize, ATTN_SMEM);

    // fused Q/K/V projections: one launch, grid.z = 3
    gemm_tc<<<dim3(DD / 64, MM / 128, 3), 256, GEMM_SMEM>>>(
        q, k, v, wq, wk, wv, bq, bk, bv, gq, gk, gv);

    attn_tc<<<dim3(SS / 128, BB * HH), 256, ATTN_SMEM>>>();

    // output projection
    gemm_tc<<<dim3(DD / 64, MM / 128, 1), 256, GEMM_SMEM>>>(
        gctx, gctx, gctx, wo, wo, wo, bo, bo, bo, out, out, out);
}

// round 6
// speedup vs baseline: 1.1601x; 1.1601x over previous
#include <cuda_runtime.h>
#include <math.h>
#include <stdint.h>

#define BB 2
#define SS 2048
#define DD 1024
#define HH 16
#define MM (BB*SS)

// Scratch (allocation-free rule: __device__ globals)
__device__ float g_Q[(size_t)MM * DD];
__device__ float g_K[(size_t)MM * DD];
__device__ float g_V[(size_t)MM * DD];
__device__ float g_ctx[(size_t)MM * DD];

__device__ __forceinline__ uint32_t f2tf(float f) {
    uint32_t u; asm("cvt.rna.tf32.f32 %0, %1;" : "=r"(u) : "f"(f)); return u;
}
__device__ __forceinline__ void mma8(float* d, const uint32_t* a, const uint32_t* b) {
    asm volatile(
        "mma.sync.aligned.m16n8k8.row.col.f32.tf32.tf32.f32 "
        "{%0,%1,%2,%3}, {%4,%5,%6,%7}, {%8,%9}, {%0,%1,%2,%3};\n"
        : "+f"(d[0]), "+f"(d[1]), "+f"(d[2]), "+f"(d[3])
        : "r"(a[0]), "r"(a[1]), "r"(a[2]), "r"(a[3]), "r"(b[0]), "r"(b[1]));
}

// ===========================================================================
// GEMM: C = A @ W + bias (tf32 mma.sync).
// Block 128x128, BK=32, 256 threads = 8 warps as 2(M) x 4(N); warp tile 64x32.
// Ping-pong SMEM, 1 barrier/chunk. grid.z selects one of up to 3 problems.
// Pads: As rows of 36, Bs rows of 136 (bank stride 8 on k like the proven 72).
// ===========================================================================
#define GPA 36
#define GPB 136
#define GA_SZ (128 * GPA)            // one A buffer (uint32 elems)
#define GB_SZ (32 * GPB)
#define GEMM_SMEM ((2 * GA_SZ + 2 * GB_SZ) * 4)   // 71680 B

__global__ void __launch_bounds__(256) gemm_tc(
    const float* __restrict__ A0, const float* __restrict__ A1, const float* __restrict__ A2,
    const float* __restrict__ W0, const float* __restrict__ W1, const float* __restrict__ W2,
    const float* __restrict__ b0, const float* __restrict__ b1, const float* __restrict__ b2,
    float* __restrict__ C0, float* __restrict__ C1, float* __restrict__ C2)
{
    extern __shared__ uint32_t gsm[];
    const int z = blockIdx.z;
    const float* A = (z == 0) ? A0 : (z == 1) ? A1 : A2;
    const float* W = (z == 0) ? W0 : (z == 1) ? W1 : W2;
    const float* bias = (z == 0) ? b0 : (z == 1) ? b1 : b2;
    float* C = (z == 0) ? C0 : (z == 1) ? C1 : C2;

    const int tid  = threadIdx.x;
    const int lane = tid & 31, warp = tid >> 5;
    const int g = lane >> 2, tig = lane & 3;
    const int wm = warp >> 2, wn = warp & 3;       // 2 x 4 warp grid
    const int row0 = blockIdx.y * 128, col0 = blockIdx.x * 128;

    // global->smem load mappings
    const int rA = tid >> 3, cA = (tid & 7) * 4;   // A: rows rA+32i, i=0..3
    const int rB = tid >> 5, cB = (tid & 31) * 4;  // B: rows rB+8i,  i=0..3
    const float* Ap = A + (size_t)(row0 + rA) * DD + cA;
    const float* Wp = W + (size_t)rB * DD + col0 + cB;

    float acc[4][4][4] = {};   // [m-tile 16][n-tile 8][frag]
    float4 av[4], wv[4];

    // ---- prologue: chunk 0 -> buf 0 ----
    #pragma unroll
    for (int i = 0; i < 4; i++) av[i] = *(const float4*)(Ap + (size_t)(32 * i) * DD);
    #pragma unroll
    for (int i = 0; i < 4; i++) wv[i] = *(const float4*)(Wp + (size_t)(8 * i) * DD);
    {
        uint32_t* As = gsm;
        uint32_t* Bs = gsm + 2 * GA_SZ;
        #pragma unroll
        for (int i = 0; i < 4; i++)
            *(uint4*)&As[(rA + 32 * i) * GPA + cA] =
                make_uint4(f2tf(av[i].x), f2tf(av[i].y), f2tf(av[i].z), f2tf(av[i].w));
        #pragma unroll
        for (int i = 0; i < 4; i++)
            *(uint4*)&Bs[(rB + 8 * i) * GPB + cB] =
                make_uint4(f2tf(wv[i].x), f2tf(wv[i].y), f2tf(wv[i].z), f2tf(wv[i].w));
    }
    __syncthreads();

    for (int c = 0; c < 32; c++) {
        // issue next-chunk global loads early (hidden under MMA loop)
        if (c + 1 < 32) {
            const int k0 = (c + 1) * 32;
            #pragma unroll
            for (int i = 0; i < 4; i++)
                av[i] = *(const float4*)(Ap + k0 + (size_t)(32 * i) * DD);
            #pragma unroll
            for (int i = 0; i < 4; i++)
                wv[i] = *(const float4*)(Wp + (size_t)(k0 + 8 * i) * DD);
        }

        const uint32_t* As = gsm + (c & 1) * GA_SZ;
        const uint32_t* Bs = gsm + 2 * GA_SZ + (c & 1) * GB_SZ;

        #pragma unroll
        for (int kk = 0; kk < 4; kk++) {
            const int kb = kk * 8;
            uint32_t af[4][4], bf[4][2];
            #pragma unroll
            for (int mt = 0; mt < 4; mt++) {
                const int r = wm * 64 + mt * 16 + g;
                af[mt][0] = As[r * GPA + kb + tig];
                af[mt][1] = As[(r + 8) * GPA + kb + tig];
                af[mt][2] = As[r * GPA + kb + tig + 4];
                af[mt][3] = As[(r + 8) * GPA + kb + tig + 4];
            }
            #pragma unroll
            for (int j = 0; j < 4; j++) {
                const int n = wn * 32 + j * 8 + g;
                bf[j][0] = Bs[(kb + tig) * GPB + n];
                bf[j][1] = Bs[(kb + tig + 4) * GPB + n];
            }
            #pragma unroll
            for (int mt = 0; mt < 4; mt++)
                #pragma unroll
                for (int j = 0; j < 4; j++)
                    mma8(acc[mt][j], af[mt], bf[j]);
        }

        // store next chunk into the other buffer, then single barrier
        if (c + 1 < 32) {
            uint32_t* Asn = gsm + ((c + 1) & 1) * GA_SZ;
            uint32_t* Bsn = gsm + 2 * GA_SZ + ((c + 1) & 1) * GB_SZ;
            #pragma unroll
            for (int i = 0; i < 4; i++)
                *(uint4*)&Asn[(rA + 32 * i) * GPA + cA] =
                    make_uint4(f2tf(av[i].x), f2tf(av[i].y), f2tf(av[i].z), f2tf(av[i].w));
            #pragma unroll
            for (int i = 0; i < 4; i++)
                *(uint4*)&Bsn[(rB + 8 * i) * GPB + cB] =
                    make_uint4(f2tf(wv[i].x), f2tf(wv[i].y), f2tf(wv[i].z), f2tf(wv[i].w));
            __syncthreads();
        }
    }

    // epilogue
    #pragma unroll
    for (int mt = 0; mt < 4; mt++) {
        #pragma unroll
        for (int j = 0; j < 4; j++) {
            const int n = col0 + wn * 32 + j * 8 + 2 * tig;
            const float bb0 = bias[n], bb1 = bias[n + 1];
            const int r = row0 + wm * 64 + mt * 16 + g;
            *(float2*)&C[(size_t)r * DD + n] =
                make_float2(acc[mt][j][0] + bb0, acc[mt][j][1] + bb1);
            *(float2*)&C[(size_t)(r + 8) * DD + n] =
                make_float2(acc[mt][j][2] + bb0, acc[mt][j][3] + bb1);
        }
    }
}

// ===========================================================================
// Flash attention, tensor-core tf32 (byte-identical to the proven R3 version).
// CTA = (128-row q-tile, b, h). 256 threads = 8 warps x 16 q-rows.
// SMEM (dynamic, 72 KB): Ks[64][72], Vs[64][72], Ps[128][72] (Q staging).
// ===========================================================================
#define APK 72

__global__ void __launch_bounds__(256) attn_tc()
{
    extern __shared__ uint32_t smem_u[];
    uint32_t* Ks = smem_u;
    uint32_t* Vs = smem_u + 64 * APK;
    uint32_t* Ps = smem_u + 128 * APK;
    float*   Qst = (float*)Ps;

    const int tid  = threadIdx.x;
    const int lane = tid & 31, warp = tid >> 5;
    const int g = lane >> 2, tig = lane & 3;
    const int qt = blockIdx.x;
    const int b  = blockIdx.y >> 4;
    const int h  = blockIdx.y & 15;

    const float* Qg = g_Q + (size_t)(b * SS + qt * 128) * DD + h * 64;
    const float* Kg = g_K + (size_t)(b * SS) * DD + h * 64;
    const float* Vg = g_V + (size_t)(b * SS) * DD + h * 64;

    {
        const int r = tid >> 4, c = (tid & 15) * 4;
        #pragma unroll
        for (int i = 0; i < 8; i++) {
            float4 qv = *(const float4*)(Qg + (size_t)(r + 16 * i) * DD + c);
            qv.x *= 0.125f; qv.y *= 0.125f; qv.z *= 0.125f; qv.w *= 0.125f;
            *(float4*)&Qst[(r + 16 * i) * APK + c] = qv;
        }
    }
    __syncthreads();

    const int qrow = warp * 16 + g;
    uint32_t qa[8][4];
    #pragma unroll
    for (int kt8 = 0; kt8 < 8; kt8++) {
        qa[kt8][0] = f2tf(Qst[qrow * APK + kt8 * 8 + tig]);
        qa[kt8][1] = f2tf(Qst[(qrow + 8) * APK + kt8 * 8 + tig]);
        qa[kt8][2] = f2tf(Qst[qrow * APK + kt8 * 8 + tig + 4]);
        qa[kt8][3] = f2tf(Qst[(qrow + 8) * APK + kt8 * 8 + tig + 4]);
    }

    float of[8][4] = {};
    float mrow[2] = {-1e30f, -1e30f};
    float lrow[2] = {0.f, 0.f};

    for (int kt = 0; kt < SS / 64; kt++) {
        __syncthreads();

        {
            const float* Kt = Kg + (size_t)(kt * 64) * DD;
            const int ck = tid & 63, fq = tid >> 6;
            #pragma unroll
            for (int g2 = 0; g2 < 4; g2++) {
                const int f = fq * 4 + g2;
                float4 kv = *(const float4*)(Kt + (size_t)ck * DD + 4 * f);
                Ks[(4 * f + 0) * APK + ck] = f2tf(kv.x);
                Ks[(4 * f + 1) * APK + ck] = f2tf(kv.y);
                Ks[(4 * f + 2) * APK + ck] = f2tf(kv.z);
                Ks[(4 * f + 3) * APK + ck] = f2tf(kv.w);
            }
        }
        {
            const float* Vt = Vg + (size_t)(kt * 64) * DD;
            const int rv = tid >> 4, cv = (tid & 15) * 4;
            #pragma unroll
            for (int i = 0; i < 4; i++) {
                float4 vv = *(const float4*)(Vt + (size_t)(rv + 16 * i) * DD + cv);
                uint4 t = make_uint4(f2tf(vv.x), f2tf(vv.y), f2tf(vv.z), f2tf(vv.w));
                *(uint4*)&Vs[(rv + 16 * i) * APK + cv] = t;
            }
        }
        __syncthreads();

        float sf[8][4] = {};
        #pragma unroll
        for (int j = 0; j < 8; j++) {
            #pragma unroll
            for (int kt8 = 0; kt8 < 8; kt8++) {
                uint32_t bb[2];
                const int kr = kt8 * 8 + tig, nc = j * 8 + g;
                bb[0] = Ks[kr * APK + nc];
                bb[1] = Ks[(kr + 4) * APK + nc];
                mma8(sf[j], qa[kt8], bb);
            }
        }

        float corr[2];
        #pragma unroll
        for (int i = 0; i < 2; i++) {
            float mx = -1e30f;
            #pragma unroll
            for (int j = 0; j < 8; j++)
                mx = fmaxf(mx, fmaxf(sf[j][2 * i], sf[j][2 * i + 1]));
            mx = fmaxf(mx, __shfl_xor_sync(0xffffffffu, mx, 1));
            mx = fmaxf(mx, __shfl_xor_sync(0xffffffffu, mx, 2));
            const float mn = fmaxf(mrow[i], mx);
            corr[i] = __expf(mrow[i] - mn);
            mrow[i] = mn;
            float rs = 0.f;
            #pragma unroll
            for (int j = 0; j < 8; j++) {
                sf[j][2 * i]     = __expf(sf[j][2 * i] - mn);
                sf[j][2 * i + 1] = __expf(sf[j][2 * i + 1] - mn);
                rs += sf[j][2 * i] + sf[j][2 * i + 1];
            }
            rs += __shfl_xor_sync(0xffffffffu, rs, 1);
            rs += __shfl_xor_sync(0xffffffffu, rs, 2);
            lrow[i] = lrow[i] * corr[i] + rs;
        }
        #pragma unroll
        for (int j = 0; j < 8; j++) {
            of[j][0] *= corr[0]; of[j][1] *= corr[0];
            of[j][2] *= corr[1]; of[j][3] *= corr[1];
        }

        #pragma unroll
        for (int j = 0; j < 8; j++) {
            uint2 p01 = make_uint2(f2tf(sf[j][0]), f2tf(sf[j][1]));
            uint2 p23 = make_uint2(f2tf(sf[j][2]), f2tf(sf[j][3]));
            *(uint2*)&Ps[qrow * APK + j * 8 + 2 * tig]       = p01;
            *(uint2*)&Ps[(qrow + 8) * APK + j * 8 + 2 * tig] = p23;
        }
        __syncthreads();

        #pragma unroll
        for (int kt8 = 0; kt8 < 8; kt8++) {
            uint32_t pa[4];
            pa[0] = Ps[qrow * APK + kt8 * 8 + tig];
            pa[1] = Ps[(qrow + 8) * APK + kt8 * 8 + tig];
            pa[2] = Ps[qrow * APK + kt8 * 8 + tig + 4];
            pa[3] = Ps[(qrow + 8) * APK + kt8 * 8 + tig + 4];
            #pragma unroll
            for (int j = 0; j < 8; j++) {
                uint32_t bb[2];
                const int vr = kt8 * 8 + tig, nc = j * 8 + g;
                bb[0] = Vs[vr * APK + nc];
                bb[1] = Vs[(vr + 4) * APK + nc];
                mma8(of[j], pa, bb);
            }
        }
    }

    const float inv0 = 1.f / lrow[0], inv1 = 1.f / lrow[1];
    const size_t orow = (size_t)(b * SS + qt * 128 + qrow);
    #pragma unroll
    for (int j = 0; j < 8; j++) {
        const int n = h * 64 + j * 8 + 2 * tig;
        *(float2*)&g_ctx[orow * DD + n] =
            make_float2(of[j][0] * inv0, of[j][1] * inv0);
        *(float2*)&g_ctx[(orow + 8) * DD + n] =
            make_float2(of[j][2] * inv1, of[j][3] * inv1);
    }
}

// ---------------------------------------------------------------------------
extern "C" void kernel_launch(void* const* d_in, const int* in_sizes, int n_in,
                              void* d_out, int out_size)
{
    (void)in_sizes; (void)n_in; (void)out_size;
    const float* q  = (const float*)d_in[0];
    const float* k  = (const float*)d_in[1];
    const float* v  = (const float*)d_in[2];
    const float* wq = (const float*)d_in[3];
    const float* bq = (const float*)d_in[4];
    const float* wk = (const float*)d_in[5];
    const float* bk = (const float*)d_in[6];
    const float* wv = (const float*)d_in[7];
    const float* bv = (const float*)d_in[8];
    const float* wo = (const float*)d_in[9];
    const float* bo = (const float*)d_in[10];
    float* out = (float*)d_out;

    float *gq, *gk, *gv, *gctx;
    cudaGetSymbolAddress((void**)&gq,   g_Q);
    cudaGetSymbolAddress((void**)&gk,   g_K);
    cudaGetSymbolAddress((void**)&gv,   g_V);
    cudaGetSymbolAddress((void**)&gctx, g_ctx);

    cudaFuncSetAttribute(gemm_tc, cudaFuncAttributeMaxDynamicSharedMemorySize, GEMM_SMEM);
    const int ATTN_SMEM = 256 * APK * 4;
    cudaFuncSetAttribute(attn_tc, cudaFuncAttributeMaxDynamicSharedMemorySize, ATTN_SMEM);

    // fused Q/K/V projections: one launch, grid.z = 3
    gemm_tc<<<dim3(DD / 128, MM / 128, 3), 256, GEMM_SMEM>>>(
        q, k, v, wq, wk, wv, bq, bk, bv, gq, gk, gv);

    attn_tc<<<dim3(SS / 128, BB * HH), 256, ATTN_SMEM>>>();

    // output projection
    gemm_tc<<<dim3(DD / 128, MM / 128, 1), 256, GEMM_SMEM>>>(
        gctx, gctx, gctx, wo, wo, wo, bo, bo, bo, out, out, out);
}

// round 7
// speedup vs baseline: 1.2618x; 1.0876x over previous
#include <cuda_runtime.h>
#include <math.h>
#include <stdint.h>

#define BB 2
#define SS 2048
#define DD 1024
#define HH 16
#define MM (BB*SS)

// Scratch (allocation-free rule: __device__ globals)
__device__ float g_Q[(size_t)MM * DD];
__device__ float g_K[(size_t)MM * DD];
__device__ float g_V[(size_t)MM * DD];
__device__ float g_ctx[(size_t)MM * DD];

__device__ __forceinline__ uint32_t f2tf(float f) {
    uint32_t u; asm("cvt.rna.tf32.f32 %0, %1;" : "=r"(u) : "f"(f)); return u;
}
__device__ __forceinline__ void mma8(float* d, const uint32_t* a, const uint32_t* b) {
    asm volatile(
        "mma.sync.aligned.m16n8k8.row.col.f32.tf32.tf32.f32 "
        "{%0,%1,%2,%3}, {%4,%5,%6,%7}, {%8,%9}, {%0,%1,%2,%3};\n"
        : "+f"(d[0]), "+f"(d[1]), "+f"(d[2]), "+f"(d[3])
        : "r"(a[0]), "r"(a[1]), "r"(a[2]), "r"(a[3]), "r"(b[0]), "r"(b[1]));
}

// ===========================================================================
// GEMM: C = A @ W + bias (tf32 mma.sync).  UNCHANGED from R5 (proven 183us).
// Block 128x128, BK=32, 256 threads = 8 warps as 2(M) x 4(N).
// ===========================================================================
#define GPA 36
#define GPB 136
#define GA_SZ (128 * GPA)
#define GB_SZ (32 * GPB)
#define GEMM_SMEM ((2 * GA_SZ + 2 * GB_SZ) * 4)   // 71680 B

__global__ void __launch_bounds__(256) gemm_tc(
    const float* __restrict__ A0, const float* __restrict__ A1, const float* __restrict__ A2,
    const float* __restrict__ W0, const float* __restrict__ W1, const float* __restrict__ W2,
    const float* __restrict__ b0, const float* __restrict__ b1, const float* __restrict__ b2,
    float* __restrict__ C0, float* __restrict__ C1, float* __restrict__ C2)
{
    extern __shared__ uint32_t gsm[];
    const int z = blockIdx.z;
    const float* A = (z == 0) ? A0 : (z == 1) ? A1 : A2;
    const float* W = (z == 0) ? W0 : (z == 1) ? W1 : W2;
    const float* bias = (z == 0) ? b0 : (z == 1) ? b1 : b2;
    float* C = (z == 0) ? C0 : (z == 1) ? C1 : C2;

    const int tid  = threadIdx.x;
    const int lane = tid & 31, warp = tid >> 5;
    const int g = lane >> 2, tig = lane & 3;
    const int wm = warp >> 2, wn = warp & 3;
    const int row0 = blockIdx.y * 128, col0 = blockIdx.x * 128;

    const int rA = tid >> 3, cA = (tid & 7) * 4;
    const int rB = tid >> 5, cB = (tid & 31) * 4;
    const float* Ap = A + (size_t)(row0 + rA) * DD + cA;
    const float* Wp = W + (size_t)rB * DD + col0 + cB;

    float acc[4][4][4] = {};
    float4 av[4], wv[4];

    #pragma unroll
    for (int i = 0; i < 4; i++) av[i] = *(const float4*)(Ap + (size_t)(32 * i) * DD);
    #pragma unroll
    for (int i = 0; i < 4; i++) wv[i] = *(const float4*)(Wp + (size_t)(8 * i) * DD);
    {
        uint32_t* As = gsm;
        uint32_t* Bs = gsm + 2 * GA_SZ;
        #pragma unroll
        for (int i = 0; i < 4; i++)
            *(uint4*)&As[(rA + 32 * i) * GPA + cA] =
                make_uint4(f2tf(av[i].x), f2tf(av[i].y), f2tf(av[i].z), f2tf(av[i].w));
        #pragma unroll
        for (int i = 0; i < 4; i++)
            *(uint4*)&Bs[(rB + 8 * i) * GPB + cB] =
                make_uint4(f2tf(wv[i].x), f2tf(wv[i].y), f2tf(wv[i].z), f2tf(wv[i].w));
    }
    __syncthreads();

    for (int c = 0; c < 32; c++) {
        if (c + 1 < 32) {
            const int k0 = (c + 1) * 32;
            #pragma unroll
            for (int i = 0; i < 4; i++)
                av[i] = *(const float4*)(Ap + k0 + (size_t)(32 * i) * DD);
            #pragma unroll
            for (int i = 0; i < 4; i++)
                wv[i] = *(const float4*)(Wp + (size_t)(k0 + 8 * i) * DD);
        }

        const uint32_t* As = gsm + (c & 1) * GA_SZ;
        const uint32_t* Bs = gsm + 2 * GA_SZ + (c & 1) * GB_SZ;

        #pragma unroll
        for (int kk = 0; kk < 4; kk++) {
            const int kb = kk * 8;
            uint32_t af[4][4], bf[4][2];
            #pragma unroll
            for (int mt = 0; mt < 4; mt++) {
                const int r = wm * 64 + mt * 16 + g;
                af[mt][0] = As[r * GPA + kb + tig];
                af[mt][1] = As[(r + 8) * GPA + kb + tig];
                af[mt][2] = As[r * GPA + kb + tig + 4];
                af[mt][3] = As[(r + 8) * GPA + kb + tig + 4];
            }
            #pragma unroll
            for (int j = 0; j < 4; j++) {
                const int n = wn * 32 + j * 8 + g;
                bf[j][0] = Bs[(kb + tig) * GPB + n];
                bf[j][1] = Bs[(kb + tig + 4) * GPB + n];
            }
            #pragma unroll
            for (int mt = 0; mt < 4; mt++)
                #pragma unroll
                for (int j = 0; j < 4; j++)
                    mma8(acc[mt][j], af[mt], bf[j]);
        }

        if (c + 1 < 32) {
            uint32_t* Asn = gsm + ((c + 1) & 1) * GA_SZ;
            uint32_t* Bsn = gsm + 2 * GA_SZ + ((c + 1) & 1) * GB_SZ;
            #pragma unroll
            for (int i = 0; i < 4; i++)
                *(uint4*)&Asn[(rA + 32 * i) * GPA + cA] =
                    make_uint4(f2tf(av[i].x), f2tf(av[i].y), f2tf(av[i].z), f2tf(av[i].w));
            #pragma unroll
            for (int i = 0; i < 4; i++)
                *(uint4*)&Bsn[(rB + 8 * i) * GPB + cB] =
                    make_uint4(f2tf(wv[i].x), f2tf(wv[i].y), f2tf(wv[i].z), f2tf(wv[i].w));
            __syncthreads();
        }
    }

    #pragma unroll
    for (int mt = 0; mt < 4; mt++) {
        #pragma unroll
        for (int j = 0; j < 4; j++) {
            const int n = col0 + wn * 32 + j * 8 + 2 * tig;
            const float bb0 = bias[n], bb1 = bias[n + 1];
            const int r = row0 + wm * 64 + mt * 16 + g;
            *(float2*)&C[(size_t)r * DD + n] =
                make_float2(acc[mt][j][0] + bb0, acc[mt][j][1] + bb1);
            *(float2*)&C[(size_t)(r + 8) * DD + n] =
                make_float2(acc[mt][j][2] + bb0, acc[mt][j][3] + bb1);
        }
    }
}

// ===========================================================================
// Flash attention, tf32 mma.sync.
// CTA = (128-row q-tile, b, h). 128 threads = 4 warps x 32 q-rows (2 m-tiles).
// B-fragments (K and V) loaded ONCE per warp and shared across both m-tiles:
// halves the dominant smem-crossbar traffic vs the 8-warp version.
// P is warp-private -> __syncwarp instead of CTA barrier after P store.
// SMEM: Ks[64][72], Vs[64][72], Ps[128][72] (Q staging overlays Ps). 72 KB.
// ===========================================================================
#define APK 72

__global__ void __launch_bounds__(128) attn_tc()
{
    extern __shared__ uint32_t smem_u[];
    uint32_t* Ks = smem_u;                 // [64][APK]
    uint32_t* Vs = smem_u + 64 * APK;      // [64][APK]
    uint32_t* Ps = smem_u + 128 * APK;     // [128][APK]
    float*   Qst = (float*)Ps;

    const int tid  = threadIdx.x;
    const int lane = tid & 31, warp = tid >> 5;
    const int g = lane >> 2, tig = lane & 3;
    const int wr0 = warp * 32;             // warp's first q-row
    const int qt = blockIdx.x;
    const int b  = blockIdx.y >> 4;
    const int h  = blockIdx.y & 15;

    const float* Qg = g_Q + (size_t)(b * SS + qt * 128) * DD + h * 64;
    const float* Kg = g_K + (size_t)(b * SS) * DD + h * 64;
    const float* Vg = g_V + (size_t)(b * SS) * DD + h * 64;

    // ---- stage Q (scaled) ----
    {
        const int r = tid >> 4, c = (tid & 15) * 4;
        #pragma unroll
        for (int i = 0; i < 16; i++) {
            float4 qv = *(const float4*)(Qg + (size_t)(r + 8 * i) * DD + c);
            qv.x *= 0.125f; qv.y *= 0.125f; qv.z *= 0.125f; qv.w *= 0.125f;
            *(float4*)&Qst[(r + 8 * i) * APK + c] = qv;
        }
    }
    __syncthreads();

    // ---- persistent Q A-fragments: 2 m-tiles x 8 k-steps ----
    uint32_t qa[2][8][4];
    #pragma unroll
    for (int mt = 0; mt < 2; mt++) {
        const int r = wr0 + mt * 16 + g;
        #pragma unroll
        for (int k8 = 0; k8 < 8; k8++) {
            qa[mt][k8][0] = f2tf(Qst[r * APK + k8 * 8 + tig]);
            qa[mt][k8][1] = f2tf(Qst[(r + 8) * APK + k8 * 8 + tig]);
            qa[mt][k8][2] = f2tf(Qst[r * APK + k8 * 8 + tig + 4]);
            qa[mt][k8][3] = f2tf(Qst[(r + 8) * APK + k8 * 8 + tig + 4]);
        }
    }

    float of[2][8][4] = {};
    float mrow[2][2] = {{-1e30f, -1e30f}, {-1e30f, -1e30f}};
    float lrow[2][2] = {{0.f, 0.f}, {0.f, 0.f}};

    for (int kt = 0; kt < SS / 64; kt++) {
        __syncthreads();   // prev tile's Ks/Vs reads complete (also orders Q)

        // K tile -> Ks[dk][key] (transposed), tf32
        {
            const float* Kt = Kg + (size_t)(kt * 64) * DD;
            const int ck = tid & 63, fq = tid >> 6;   // fq in {0,1}
            #pragma unroll
            for (int g2 = 0; g2 < 8; g2++) {
                const int f = fq * 8 + g2;
                float4 kv = *(const float4*)(Kt + (size_t)ck * DD + 4 * f);
                Ks[(4 * f + 0) * APK + ck] = f2tf(kv.x);
                Ks[(4 * f + 1) * APK + ck] = f2tf(kv.y);
                Ks[(4 * f + 2) * APK + ck] = f2tf(kv.z);
                Ks[(4 * f + 3) * APK + ck] = f2tf(kv.w);
            }
        }
        // V tile -> Vs[key][dk], tf32
        {
            const float* Vt = Vg + (size_t)(kt * 64) * DD;
            const int rv = tid >> 4, cv = (tid & 15) * 4;
            #pragma unroll
            for (int i = 0; i < 8; i++) {
                float4 vv = *(const float4*)(Vt + (size_t)(rv + 8 * i) * DD + cv);
                uint4 t = make_uint4(f2tf(vv.x), f2tf(vv.y), f2tf(vv.z), f2tf(vv.w));
                *(uint4*)&Vs[(rv + 8 * i) * APK + cv] = t;
            }
        }
        __syncthreads();

        // ---- S = Qs @ K^T : bf loaded once, shared across both m-tiles ----
        float sf[2][8][4] = {};
        #pragma unroll
        for (int k8 = 0; k8 < 8; k8++) {
            const int kr = k8 * 8 + tig;
            uint32_t bf[8][2];
            #pragma unroll
            for (int j = 0; j < 8; j++) {
                bf[j][0] = Ks[kr * APK + j * 8 + g];
                bf[j][1] = Ks[(kr + 4) * APK + j * 8 + g];
            }
            #pragma unroll
            for (int mt = 0; mt < 2; mt++)
                #pragma unroll
                for (int j = 0; j < 8; j++)
                    mma8(sf[mt][j], qa[mt][k8], bf[j]);
        }

        // ---- online softmax (per m-tile, per row-half) ----
        #pragma unroll
        for (int mt = 0; mt < 2; mt++) {
            #pragma unroll
            for (int i = 0; i < 2; i++) {
                float mx = -1e30f;
                #pragma unroll
                for (int j = 0; j < 8; j++)
                    mx = fmaxf(mx, fmaxf(sf[mt][j][2 * i], sf[mt][j][2 * i + 1]));
                mx = fmaxf(mx, __shfl_xor_sync(0xffffffffu, mx, 1));
                mx = fmaxf(mx, __shfl_xor_sync(0xffffffffu, mx, 2));
                const float mn = fmaxf(mrow[mt][i], mx);
                const float corr = __expf(mrow[mt][i] - mn);
                mrow[mt][i] = mn;
                float rs = 0.f;
                #pragma unroll
                for (int j = 0; j < 8; j++) {
                    sf[mt][j][2 * i]     = __expf(sf[mt][j][2 * i] - mn);
                    sf[mt][j][2 * i + 1] = __expf(sf[mt][j][2 * i + 1] - mn);
                    rs += sf[mt][j][2 * i] + sf[mt][j][2 * i + 1];
                }
                rs += __shfl_xor_sync(0xffffffffu, rs, 1);
                rs += __shfl_xor_sync(0xffffffffu, rs, 2);
                lrow[mt][i] = lrow[mt][i] * corr + rs;
                #pragma unroll
                for (int j = 0; j < 8; j++) {
                    of[mt][j][2 * i]     *= corr;
                    of[mt][j][2 * i + 1] *= corr;
                }
            }
        }

        // ---- P -> Ps (tf32); warp-private region -> warp sync only ----
        #pragma unroll
        for (int mt = 0; mt < 2; mt++) {
            const int r = wr0 + mt * 16 + g;
            #pragma unroll
            for (int j = 0; j < 8; j++) {
                *(uint2*)&Ps[r * APK + j * 8 + 2 * tig] =
                    make_uint2(f2tf(sf[mt][j][0]), f2tf(sf[mt][j][1]));
                *(uint2*)&Ps[(r + 8) * APK + j * 8 + 2 * tig] =
                    make_uint2(f2tf(sf[mt][j][2]), f2tf(sf[mt][j][3]));
            }
        }
        __syncwarp();

        // ---- O += P @ V : bb loaded once, shared across both m-tiles ----
        #pragma unroll
        for (int k8 = 0; k8 < 8; k8++) {
            const int vr = k8 * 8 + tig;
            uint32_t pa[2][4];
            #pragma unroll
            for (int mt = 0; mt < 2; mt++) {
                const int r = wr0 + mt * 16 + g;
                pa[mt][0] = Ps[r * APK + k8 * 8 + tig];
                pa[mt][1] = Ps[(r + 8) * APK + k8 * 8 + tig];
                pa[mt][2] = Ps[r * APK + k8 * 8 + tig + 4];
                pa[mt][3] = Ps[(r + 8) * APK + k8 * 8 + tig + 4];
            }
            #pragma unroll
            for (int j = 0; j < 8; j++) {
                uint32_t bb[2];
                bb[0] = Vs[vr * APK + j * 8 + g];
                bb[1] = Vs[(vr + 4) * APK + j * 8 + g];
                #pragma unroll
                for (int mt = 0; mt < 2; mt++)
                    mma8(of[mt][j], pa[mt], bb);
            }
        }
    }

    // ---- normalize + write context ----
    #pragma unroll
    for (int mt = 0; mt < 2; mt++) {
        const float inv0 = 1.f / lrow[mt][0], inv1 = 1.f / lrow[mt][1];
        const size_t orow = (size_t)(b * SS + qt * 128 + wr0 + mt * 16 + g);
        #pragma unroll
        for (int j = 0; j < 8; j++) {
            const int n = h * 64 + j * 8 + 2 * tig;
            *(float2*)&g_ctx[orow * DD + n] =
                make_float2(of[mt][j][0] * inv0, of[mt][j][1] * inv0);
            *(float2*)&g_ctx[(orow + 8) * DD + n] =
                make_float2(of[mt][j][2] * inv1, of[mt][j][3] * inv1);
        }
    }
}

// ---------------------------------------------------------------------------
extern "C" void kernel_launch(void* const* d_in, const int* in_sizes, int n_in,
                              void* d_out, int out_size)
{
    (void)in_sizes; (void)n_in; (void)out_size;
    const float* q  = (const float*)d_in[0];
    const float* k  = (const float*)d_in[1];
    const float* v  = (const float*)d_in[2];
    const float* wq = (const float*)d_in[3];
    const float* bq = (const float*)d_in[4];
    const float* wk = (const float*)d_in[5];
    const float* bk = (const float*)d_in[6];
    const float* wv = (const float*)d_in[7];
    const float* bv = (const float*)d_in[8];
    const float* wo = (const float*)d_in[9];
    const float* bo = (const float*)d_in[10];
    float* out = (float*)d_out;

    float *gq, *gk, *gv, *gctx;
    cudaGetSymbolAddress((void**)&gq,   g_Q);
    cudaGetSymbolAddress((void**)&gk,   g_K);
    cudaGetSymbolAddress((void**)&gv,   g_V);
    cudaGetSymbolAddress((void**)&gctx, g_ctx);

    cudaFuncSetAttribute(gemm_tc, cudaFuncAttributeMaxDynamicSharedMemorySize, GEMM_SMEM);
    const int ATTN_SMEM = 256 * APK * 4;   // 73728 B
    cudaFuncSetAttribute(attn_tc, cudaFuncAttributeMaxDynamicSharedMemorySize, ATTN_SMEM);

    // fused Q/K/V projections: one launch, grid.z = 3
    gemm_tc<<<dim3(DD / 128, MM / 128, 3), 256, GEMM_SMEM>>>(
        q, k, v, wq, wk, wv, bq, bk, bv, gq, gk, gv);

    attn_tc<<<dim3(SS / 128, BB * HH), 128, ATTN_SMEM>>>();

    // output projection
    gemm_tc<<<dim3(DD / 128, MM / 128, 1), 256, GEMM_SMEM>>>(
        gctx, gctx, gctx, wo, wo, wo, bo, bo, bo, out, out, out);
}